// round 5
// baseline (speedup 1.0000x reference)
#include <cuda_runtime.h>
#include <cstdint>
#include <math.h>

// Problem constants
#define BB 64
#define TT 512
#define DD 512
#define HH 1024
#define G4 4096   // 4*H
#define NBLK 128

// ---------------- device scratch (no cudaMalloc allowed) ----------------
__device__ float g_xg[(size_t)BB * TT * G4];   // input projection + biases (512 MB)
__device__ float g_h[2][BB * HH];              // double-buffered hidden state
__device__ float g_c[BB * HH];                 // cell state (CTA-exclusive columns)
__device__ unsigned g_bar;                     // grid barrier counter (reset by xg_gemm)

// ---------------- f32x2 packed-FMA helpers ----------------
__device__ __forceinline__ void fma2(unsigned long long& d,
                                     unsigned long long a, unsigned long long b) {
    asm("fma.rn.f32x2 %0, %1, %2, %0;" : "+l"(d) : "l"(a), "l"(b));
}
__device__ __forceinline__ unsigned long long bcast2(float x) {
    unsigned long long r;
    asm("mov.b64 %0, {%1, %1};" : "=l"(r) : "f"(x));
    return r;
}
__device__ __forceinline__ float2 unpack2(unsigned long long d) {
    float2 v;
    asm("mov.b64 {%0, %1}, %2;" : "=f"(v.x), "=f"(v.y) : "l"(d));
    return v;
}

// ---------------- TMA bulk + mbarrier helpers ----------------
__device__ __forceinline__ unsigned smem_u32(const void* p) {
    return (unsigned)__cvta_generic_to_shared(p);
}
__device__ __forceinline__ void mbar_init(unsigned addr, unsigned count) {
    asm volatile("mbarrier.init.shared.b64 [%0], %1;" :: "r"(addr), "r"(count) : "memory");
}
__device__ __forceinline__ void mbar_expect_tx(unsigned addr, unsigned bytes) {
    asm volatile("mbarrier.arrive.expect_tx.shared.b64 _, [%0], %1;"
                 :: "r"(addr), "r"(bytes) : "memory");
}
__device__ __forceinline__ void mbar_wait(unsigned addr, unsigned parity) {
    asm volatile(
        "{\n\t.reg .pred P;\n"
        "W_%=:\n\t"
        "mbarrier.try_wait.parity.acquire.cta.shared::cta.b64 P, [%0], %1, 0x989680;\n\t"
        "@P bra D_%=;\n\t"
        "bra W_%=;\n"
        "D_%=:\n\t}"
        :: "r"(addr), "r"(parity) : "memory");
}
__device__ __forceinline__ void bulk_cp(void* sdst, const void* gsrc,
                                        unsigned bytes, unsigned mbar) {
    unsigned d = smem_u32(sdst);
    asm volatile(
        "cp.async.bulk.shared::cluster.global.mbarrier::complete_tx::bytes [%0], [%1], %2, [%3];"
        :: "r"(d), "l"(gsrc), "r"(bytes), "r"(mbar) : "memory");
}

// ---------------- xg GEMM (FFMA2 inner loop) + g_bar reset ----------------
#define BM 128
#define BN 128
#define BK 16
__global__ __launch_bounds__(256, 2)
void xg_gemm(const float* __restrict__ X, const float* __restrict__ Wih,
             const float* __restrict__ bih, const float* __restrict__ bhh) {
    if (blockIdx.x == 0 && blockIdx.y == 0 && threadIdx.x == 0) g_bar = 0u;

    __shared__ float As[BK][BM + 4];
    __shared__ float Bs[BK][BN + 4];

    int tid = threadIdx.x;
    int bm = blockIdx.y;
    int bn = blockIdx.x;

    int trow = (tid / 16) * 8;
    int tcol = (tid % 16) * 8;

    const float* Aofs = X   + (size_t)bm * BM * DD;
    const float* Bofs = Wih + (size_t)bn * BN * DD;

    int a_r = tid >> 2;
    int a_c = (tid & 3) * 4;

    unsigned long long acc[8][4];
#pragma unroll
    for (int i = 0; i < 8; i++)
#pragma unroll
        for (int p = 0; p < 4; p++) acc[i][p] = 0ull;

    for (int k0 = 0; k0 < DD; k0 += BK) {
#pragma unroll
        for (int i = 0; i < 2; i++) {
            float4 v = *(const float4*)(Aofs + (size_t)(a_r + i * 64) * DD + k0 + a_c);
            As[a_c + 0][a_r + i * 64] = v.x;
            As[a_c + 1][a_r + i * 64] = v.y;
            As[a_c + 2][a_r + i * 64] = v.z;
            As[a_c + 3][a_r + i * 64] = v.w;
        }
#pragma unroll
        for (int i = 0; i < 2; i++) {
            float4 v = *(const float4*)(Bofs + (size_t)(a_r + i * 64) * DD + k0 + a_c);
            Bs[a_c + 0][a_r + i * 64] = v.x;
            Bs[a_c + 1][a_r + i * 64] = v.y;
            Bs[a_c + 2][a_r + i * 64] = v.z;
            Bs[a_c + 3][a_r + i * 64] = v.w;
        }
        __syncthreads();
#pragma unroll
        for (int kk = 0; kk < BK; kk++) {
            ulonglong2 b0 = *(const ulonglong2*)(&Bs[kk][tcol]);
            ulonglong2 b1 = *(const ulonglong2*)(&Bs[kk][tcol + 4]);
            float4 a0 = *(const float4*)(&As[kk][trow]);
            float4 a1 = *(const float4*)(&As[kk][trow + 4]);
            float av[8] = {a0.x, a0.y, a0.z, a0.w, a1.x, a1.y, a1.z, a1.w};
#pragma unroll
            for (int i = 0; i < 8; i++) {
                unsigned long long ab = bcast2(av[i]);
                fma2(acc[i][0], ab, b0.x);
                fma2(acc[i][1], ab, b0.y);
                fma2(acc[i][2], ab, b1.x);
                fma2(acc[i][3], ab, b1.y);
            }
        }
        __syncthreads();
    }

    float bias[8];
#pragma unroll
    for (int j = 0; j < 8; j++) {
        int g = bn * BN + tcol + j;
        bias[j] = bih[g] + bhh[g];
    }
#pragma unroll
    for (int i = 0; i < 8; i++) {
        size_t row = (size_t)(bm * BM + trow + i);
        float* op = g_xg + row * G4 + bn * BN + tcol;
#pragma unroll
        for (int p2 = 0; p2 < 2; p2++) {
            float2 u0 = unpack2(acc[i][p2 * 2 + 0]);
            float2 u1 = unpack2(acc[i][p2 * 2 + 1]);
            float4 v;
            v.x = u0.x + bias[p2 * 4 + 0];
            v.y = u0.y + bias[p2 * 4 + 1];
            v.z = u1.x + bias[p2 * 4 + 2];
            v.w = u1.y + bias[p2 * 4 + 3];
            *(float4*)(op + p2 * 4) = v;
        }
    }
}

// ---------------- persistent LSTM recurrence ----------------
#define KC 128
#define WS_STRIDE 36
#define HROW 132          // 132 floats = 528 B (16B aligned), pad kills bank conflicts
// dynamic smem floats: Ws 1024*36=36864 | hs 2*64*132=16896 | gsm 8*8*33=2112
#define SMEM_FLOATS (36864 + 16896 + 2112)
#define SMEM_BYTES  (SMEM_FLOATS * 4)

__device__ __forceinline__ float sigm(float x) { return 1.f / (1.f + expf(-x)); }

__global__ __launch_bounds__(256, 1)
void lstm_persistent(const float* __restrict__ Whh, const int* __restrict__ mask,
                     const float* __restrict__ h0, const float* __restrict__ c0,
                     float* __restrict__ out) {
    extern __shared__ float sm[];
    float* Ws  = sm;                       // [1024][36]
    float* hs  = sm + 1024 * WS_STRIDE;    // [2][64][HROW]
    float* gsm = hs + 2 * 64 * HROW;       // per-warp [8][33] gate stash

    __shared__ int act[BB], inact[BB];
    __shared__ unsigned ballots[2];
    __shared__ __align__(8) unsigned long long mbar_store[2];

    int tid  = threadIdx.x;
    int base = blockIdx.x * 8;
    int w    = tid >> 5, lane = tid & 31;
    int q    = lane >> 3, c = lane & 7;
    int r0   = w * 8 + q * 2;

    unsigned mb0 = smem_u32(&mbar_store[0]);
    unsigned mb1 = smem_u32(&mbar_store[1]);
    if (tid == 0) { mbar_init(mb0, 1); mbar_init(mb1, 1); }
    int ph0 = 0, ph1 = 0;

    // ---- init state (own columns), W slice load ----
    for (int i = tid; i < BB * 8; i += 256) {   // i = b*8 + u
        int b = i >> 3, u = i & 7;
        int col = base + u;
        g_h[0][b * HH + col] = h0[col];
        g_c[b * HH + col]    = c0[col];
    }
    for (int i = tid; i < 32 * 256; i += 256) {
        int col = i >> 8;
        int k4  = (i & 255) * 4;
        int gate = col >> 3, u = col & 7;
        const float* wp = Whh + ((size_t)(gate * HH + base + u)) * HH + k4;
        float4 v = *(const float4*)wp;
        Ws[(k4 + 0) * WS_STRIDE + col] = v.x;
        Ws[(k4 + 1) * WS_STRIDE + col] = v.y;
        Ws[(k4 + 2) * WS_STRIDE + col] = v.z;
        Ws[(k4 + 3) * WS_STRIDE + col] = v.w;
    }
    __syncthreads();

    // grid barrier gen 1: h init visible to all CTAs (staging reads ALL columns)
    if (tid == 0) {
        __threadfence();
        atomicAdd(&g_bar, 1u);
        while (*(volatile unsigned*)&g_bar < NBLK) { __nanosleep(64); }
    }
    __syncthreads();
    __threadfence();

    // mask prefetch register (threads 0..63 hold row tid's mask for step t)
    int mreg = 0;
    if (tid < BB) mreg = mask[tid * TT + 0];

    for (int t = 0; t < TT; t++) {
        const float* hcur  = g_h[t & 1];
        float*       hnext = g_h[(t + 1) & 1];

        // ---- ballot compaction ----
        if (tid < BB) {
            unsigned bal = __ballot_sync(0xffffffff, mreg != 0);
            if ((tid & 31) == 0) ballots[tid >> 5] = bal;
        }
        __syncthreads();
        unsigned b0 = ballots[0], b1 = ballots[1];
        int nact = __popc(b0) + __popc(b1);
        if (tid < BB) {
            unsigned bal = (tid < 32) ? b0 : b1;
            unsigned lt  = (1u << (tid & 31)) - 1u;
            int oneslt  = __popc(bal & lt) + ((tid < 32) ? 0 : __popc(b0));
            int zeroslt = (tid & 31) - __popc(bal & lt) + ((tid < 32) ? 0 : 32 - __popc(b0));
            if (mreg) act[oneslt] = tid; else inact[zeroslt] = tid;
            // prefetch next step's mask
            if (t + 1 < TT) mreg = mask[tid * TT + t + 1];
        }
        __syncthreads();
        int ninact = BB - nact;

        // ---- inactive rows: pass-through ----
        for (int i = tid; i < ninact * 8; i += 256) {
            int r = i >> 3, u = i & 7;
            int b = inact[r];
            int idx = b * HH + base + u;
            float v = __ldcg(hcur + idx);
            hnext[idx] = v;
            out[((size_t)b * TT + t) * HH + base + u] = v;
        }

        unsigned long long acc00 = 0ull, acc01 = 0ull, acc10 = 0ull, acc11 = 0ull;
        bool wact = (w * 8 < nact);

        // ---- prologue: bulk-stage chunk 0 -> buf 0 ----
        if (tid == 0) mbar_expect_tx(mb0, (unsigned)nact * 512u);
        if (tid < nact) {
            bulk_cp(hs + (size_t)tid * HROW,
                    hcur + (size_t)act[tid] * HH, 512u, mb0);
        }

        // ---- main K loop: 8 chunks, TMA double-buffered ----
        for (int ch = 0; ch < 8; ch++) {
            unsigned mbc = (ch & 1) ? mb1 : mb0;
            int& phc = (ch & 1) ? ph1 : ph0;
            mbar_wait(mbc, (unsigned)phc);
            phc ^= 1;

            if (ch + 1 < 8) {
                __syncthreads();   // all warps done FMA(ch-1) before overwriting its buffer
                unsigned mbn = ((ch + 1) & 1) ? mb1 : mb0;
                float* dstb = hs + (size_t)((ch + 1) & 1) * 64 * HROW;
                if (tid == 0) mbar_expect_tx(mbn, (unsigned)nact * 512u);
                if (tid < nact) {
                    bulk_cp(dstb + (size_t)tid * HROW,
                            hcur + (size_t)act[tid] * HH + (ch + 1) * KC, 512u, mbn);
                }
            }

            if (wact) {
                const float* wp = Ws + (size_t)(ch * KC) * WS_STRIDE + c * 4;
                const float* hp = hs + (size_t)(ch & 1) * 64 * HROW + (size_t)r0 * HROW;
#pragma unroll 4
                for (int kk = 0; kk < KC; kk += 2) {
                    ulonglong2 w0 = *(const ulonglong2*)(wp + (size_t)kk * WS_STRIDE);
                    ulonglong2 w1 = *(const ulonglong2*)(wp + (size_t)(kk + 1) * WS_STRIDE);
                    float2 ha = *(const float2*)(hp + kk);
                    float2 hb = *(const float2*)(hp + HROW + kk);
                    unsigned long long hax = bcast2(ha.x), hbx = bcast2(hb.x);
                    fma2(acc00, hax, w0.x); fma2(acc01, hax, w0.y);
                    fma2(acc10, hbx, w0.x); fma2(acc11, hbx, w0.y);
                    unsigned long long hay = bcast2(ha.y), hby = bcast2(hb.y);
                    fma2(acc00, hay, w1.x); fma2(acc01, hay, w1.y);
                    fma2(acc10, hby, w1.x); fma2(acc11, hby, w1.y);
                }
            }
        }

        // ---- epilogue ----
        float accf[2][4];
        {
            float2 u;
            u = unpack2(acc00); accf[0][0] = u.x; accf[0][1] = u.y;
            u = unpack2(acc01); accf[0][2] = u.x; accf[0][3] = u.y;
            u = unpack2(acc10); accf[1][0] = u.x; accf[1][1] = u.y;
            u = unpack2(acc11); accf[1][2] = u.x; accf[1][3] = u.y;
        }
        float* gw = gsm + w * (8 * 33);
        if (wact) {
            int gate = c >> 1;
            int gg0  = gate * HH + base + (c & 1) * 4;
#pragma unroll
            for (int i = 0; i < 2; i++) {
                int r = r0 + i;
                if (r < nact) {
                    int b = act[r];
                    float4 xv = *(const float4*)(g_xg + ((size_t)b * TT + t) * G4 + gg0);
                    int rl = q * 2 + i;
                    gw[rl * 33 + c * 4 + 0] = accf[i][0] + xv.x;
                    gw[rl * 33 + c * 4 + 1] = accf[i][1] + xv.y;
                    gw[rl * 33 + c * 4 + 2] = accf[i][2] + xv.z;
                    gw[rl * 33 + c * 4 + 3] = accf[i][3] + xv.w;
                }
            }
        }
        __syncwarp();
        if (wact) {
#pragma unroll
            for (int ee = 0; ee < 2; ee++) {
                int e = lane * 2 + ee;
                int rl = e >> 3, u = e & 7;
                int r = w * 8 + rl;
                if (r < nact) {
                    int b = act[r];
                    float gi = gw[rl * 33 + u];
                    float gf = gw[rl * 33 + 8 + u];
                    float gG = gw[rl * 33 + 16 + u];
                    float go = gw[rl * 33 + 24 + u];
                    float iv = sigm(gi);
                    float fv = sigm(gf);
                    float gv = tanhf(gG);
                    float ov = sigm(go);
                    int idx = b * HH + base + u;
                    float cn = fv * g_c[idx] + iv * gv;
                    float hn = ov * tanhf(cn);
                    g_c[idx] = cn;
                    hnext[idx] = hn;
                    out[((size_t)b * TT + t) * HH + base + u] = hn;
                }
            }
        }

        // ---- grid barrier, generation t+2 ----
        __syncthreads();
        if (tid == 0) {
            __threadfence();
            atomicAdd(&g_bar, 1u);
            unsigned want = (unsigned)(t + 2) * NBLK;
            while (*(volatile unsigned*)&g_bar < want) { __nanosleep(64); }
        }
        __syncthreads();
        __threadfence();
    }
}

// ---------------- launch ----------------
extern "C" void kernel_launch(void* const* d_in, const int* in_sizes, int n_in,
                              void* d_out, int out_size) {
    const float* x    = (const float*)d_in[0];
    const int*   mask = (const int*)  d_in[1];
    const float* Wih  = (const float*)d_in[2];
    const float* Whh  = (const float*)d_in[3];
    const float* bih  = (const float*)d_in[4];
    const float* bhh  = (const float*)d_in[5];
    const float* h0   = (const float*)d_in[6];
    const float* c0   = (const float*)d_in[7];
    float* out = (float*)d_out;

    cudaFuncSetAttribute(lstm_persistent, cudaFuncAttributeMaxDynamicSharedMemorySize, SMEM_BYTES);

    xg_gemm<<<dim3(G4 / BN, (BB * TT) / BM), 256>>>(x, Wih, bih, bhh);
    lstm_persistent<<<NBLK, 256, SMEM_BYTES>>>(Whh, mask, h0, c0, out);
}

// round 7
// speedup vs baseline: 1.6462x; 1.6462x over previous
#include <cuda_runtime.h>
#include <cuda_bf16.h>
#include <cstdint>
#include <math.h>

#define BB 64
#define TT 512
#define DD 512
#define HH 1024
#define G4 4096
#define NBLK 128

#define AROW 272                 // bytes per row in an h chunk block (16 blocks + 1 pad)
#define CHUNK_BYTES (128 * AROW) // 34816
#define WROW 2064                // bytes per W row in SMEM (1024 bf16 + 16B pad)

// ---------------- device scratch ----------------
__device__ float g_xg[(size_t)BB * TT * G4];
__device__ __align__(16) unsigned char g_hA[2][8 * CHUNK_BYTES]; // h hi/lo bf16 chunk blocks
__device__ unsigned g_bar;

// ---------------- f32x2 helpers (xg gemm) ----------------
__device__ __forceinline__ void fma2(unsigned long long& d, unsigned long long a, unsigned long long b) {
    asm("fma.rn.f32x2 %0, %1, %2, %0;" : "+l"(d) : "l"(a), "l"(b));
}
__device__ __forceinline__ unsigned long long bcast2(float x) {
    unsigned long long r; asm("mov.b64 %0, {%1, %1};" : "=l"(r) : "f"(x)); return r;
}
__device__ __forceinline__ float2 unpack2(unsigned long long d) {
    float2 v; asm("mov.b64 {%0, %1}, %2;" : "=f"(v.x), "=f"(v.y) : "l"(d)); return v;
}

// ---------------- mbarrier / bulk-copy helpers ----------------
__device__ __forceinline__ unsigned smem_u32(const void* p) {
    return (unsigned)__cvta_generic_to_shared(p);
}
__device__ __forceinline__ void mbar_init(unsigned a, unsigned n) {
    asm volatile("mbarrier.init.shared.b64 [%0], %1;" :: "r"(a), "r"(n) : "memory");
}
__device__ __forceinline__ void mbar_expect_tx(unsigned a, unsigned b) {
    asm volatile("mbarrier.arrive.expect_tx.shared.b64 _, [%0], %1;" :: "r"(a), "r"(b) : "memory");
}
__device__ __forceinline__ void mbar_wait(unsigned a, unsigned p) {
    asm volatile(
        "{\n\t.reg .pred P;\n"
        "W_%=:\n\t"
        "mbarrier.try_wait.parity.acquire.cta.shared::cta.b64 P, [%0], %1, 0x989680;\n\t"
        "@P bra D_%=;\n\t"
        "bra W_%=;\n"
        "D_%=:\n\t}" :: "r"(a), "r"(p) : "memory");
}
__device__ __forceinline__ void bulk_cp(void* sdst, const void* gsrc, unsigned bytes, unsigned mbar) {
    unsigned d = smem_u32(sdst);
    asm volatile(
        "cp.async.bulk.shared::cluster.global.mbarrier::complete_tx::bytes [%0], [%1], %2, [%3];"
        :: "r"(d), "l"(gsrc), "r"(bytes), "r"(mbar) : "memory");
}

// ---------------- bf16 mma.sync (HMMA, sm_80+ PTX — compiles for sm_103) ----------------
__device__ __forceinline__ void mma_bf16(float* c, unsigned a0, unsigned a1, unsigned a2, unsigned a3,
                                         unsigned b0, unsigned b1) {
    asm volatile(
        "mma.sync.aligned.m16n8k16.row.col.f32.bf16.bf16.f32 "
        "{%0,%1,%2,%3}, {%4,%5,%6,%7}, {%8,%9}, {%0,%1,%2,%3};"
        : "+f"(c[0]), "+f"(c[1]), "+f"(c[2]), "+f"(c[3])
        : "r"(a0), "r"(a1), "r"(a2), "r"(a3), "r"(b0), "r"(b1));
}

__device__ __forceinline__ unsigned pack_hi(float v0, float v1, float& l0, float& l1) {
    __nv_bfloat16 h0 = __float2bfloat16_rn(v0), h1 = __float2bfloat16_rn(v1);
    l0 = v0 - __bfloat162float(h0);
    l1 = v1 - __bfloat162float(h1);
    unsigned short u0 = *(unsigned short*)&h0, u1 = *(unsigned short*)&h1;
    return (unsigned)u0 | ((unsigned)u1 << 16);
}
__device__ __forceinline__ unsigned pack_lo(float l0, float l1) {
    __nv_bfloat16 a = __float2bfloat16_rn(l0), b = __float2bfloat16_rn(l1);
    unsigned short u0 = *(unsigned short*)&a, u1 = *(unsigned short*)&b;
    return (unsigned)u0 | ((unsigned)u1 << 16);
}
__device__ __forceinline__ float sigm(float x) { return 1.f / (1.f + expf(-x)); }

// ---------------- xg GEMM (unchanged) ----------------
#define BM 128
#define BN 128
#define BK 16
__global__ __launch_bounds__(256, 2)
void xg_gemm(const float* __restrict__ X, const float* __restrict__ Wih,
             const float* __restrict__ bih, const float* __restrict__ bhh) {
    if (blockIdx.x == 0 && blockIdx.y == 0 && threadIdx.x == 0) g_bar = 0u;
    __shared__ float As[BK][BM + 4];
    __shared__ float Bs[BK][BN + 4];
    int tid = threadIdx.x, bm = blockIdx.y, bn = blockIdx.x;
    int trow = (tid / 16) * 8, tcol = (tid % 16) * 8;
    const float* Aofs = X + (size_t)bm * BM * DD;
    const float* Bofs = Wih + (size_t)bn * BN * DD;
    int a_r = tid >> 2, a_c = (tid & 3) * 4;

    unsigned long long acc[8][4];
#pragma unroll
    for (int i = 0; i < 8; i++)
#pragma unroll
        for (int p = 0; p < 4; p++) acc[i][p] = 0ull;

    for (int k0 = 0; k0 < DD; k0 += BK) {
#pragma unroll
        for (int i = 0; i < 2; i++) {
            float4 v = *(const float4*)(Aofs + (size_t)(a_r + i * 64) * DD + k0 + a_c);
            As[a_c + 0][a_r + i * 64] = v.x; As[a_c + 1][a_r + i * 64] = v.y;
            As[a_c + 2][a_r + i * 64] = v.z; As[a_c + 3][a_r + i * 64] = v.w;
        }
#pragma unroll
        for (int i = 0; i < 2; i++) {
            float4 v = *(const float4*)(Bofs + (size_t)(a_r + i * 64) * DD + k0 + a_c);
            Bs[a_c + 0][a_r + i * 64] = v.x; Bs[a_c + 1][a_r + i * 64] = v.y;
            Bs[a_c + 2][a_r + i * 64] = v.z; Bs[a_c + 3][a_r + i * 64] = v.w;
        }
        __syncthreads();
#pragma unroll
        for (int kk = 0; kk < BK; kk++) {
            ulonglong2 b0 = *(const ulonglong2*)(&Bs[kk][tcol]);
            ulonglong2 b1 = *(const ulonglong2*)(&Bs[kk][tcol + 4]);
            float4 a0 = *(const float4*)(&As[kk][trow]);
            float4 a1 = *(const float4*)(&As[kk][trow + 4]);
            float av[8] = {a0.x, a0.y, a0.z, a0.w, a1.x, a1.y, a1.z, a1.w};
#pragma unroll
            for (int i = 0; i < 8; i++) {
                unsigned long long ab = bcast2(av[i]);
                fma2(acc[i][0], ab, b0.x); fma2(acc[i][1], ab, b0.y);
                fma2(acc[i][2], ab, b1.x); fma2(acc[i][3], ab, b1.y);
            }
        }
        __syncthreads();
    }
    float bias[8];
#pragma unroll
    for (int j = 0; j < 8; j++) { int g = bn * BN + tcol + j; bias[j] = bih[g] + bhh[g]; }
#pragma unroll
    for (int i = 0; i < 8; i++) {
        size_t row = (size_t)(bm * BM + trow + i);
        float* op = g_xg + row * G4 + bn * BN + tcol;
#pragma unroll
        for (int p2 = 0; p2 < 2; p2++) {
            float2 u0 = unpack2(acc[i][p2 * 2 + 0]);
            float2 u1 = unpack2(acc[i][p2 * 2 + 1]);
            float4 v;
            v.x = u0.x + bias[p2 * 4 + 0]; v.y = u0.y + bias[p2 * 4 + 1];
            v.z = u1.x + bias[p2 * 4 + 2]; v.w = u1.y + bias[p2 * 4 + 3];
            *(float4*)(op + p2 * 4) = v;
        }
    }
}

// ---------------- persistent HMMA LSTM ----------------
// SMEM: A0, A1 (34816 each) | Whi, Wlo (66048 each) | stash 64x33 f32 (8448)
#define SM_A0 0
#define SM_A1 CHUNK_BYTES
#define SM_WHI (2 * CHUNK_BYTES)
#define SM_WLO (2 * CHUNK_BYTES + 32 * WROW)
#define SM_STASH (2 * CHUNK_BYTES + 64 * WROW)
#define SMEM_BYTES (SM_STASH + 8448 + 1024)

__global__ __launch_bounds__(128, 1)
void lstm_tc(const float* __restrict__ Whh, const int* __restrict__ mask,
             const float* __restrict__ h0, const float* __restrict__ c0,
             float* __restrict__ out) {
    extern __shared__ char smraw[];
    char* smb = (char*)(((uintptr_t)smraw + 1023) & ~(uintptr_t)1023);
    char* Abuf[2] = { smb + SM_A0, smb + SM_A1 };
    char* Whi = smb + SM_WHI;
    char* Wlo = smb + SM_WLO;
    float* stash = (float*)(smb + SM_STASH);   // [64][33]

    __shared__ __align__(8) unsigned long long mbst[2];

    int tid = threadIdx.x;
    int w = tid >> 5, lane = tid & 31;
    int g = lane >> 2, tig = lane & 3;
    int base = blockIdx.x * 8;
    int ch_base = base >> 7;
    int cb_base = (base & 127) >> 3;

    unsigned mbA[2] = { smem_u32(&mbst[0]), smem_u32(&mbst[1]) };
    if (tid == 0) { mbar_init(mbA[0], 1); mbar_init(mbA[1], 1); }

    // ---- build W hi/lo tiles once: row n = gate*8+u, [n][k] bf16, stride WROW ----
    for (int idx = tid; idx < 32 * 128; idx += 128) {
        int n = idx >> 7, k = (idx & 127) * 8;
        int gg = n >> 3, u = n & 7;
        const float* wp = Whh + ((size_t)(gg * HH + base + u)) * HH + k;
        float4 v0 = *(const float4*)wp, v1 = *(const float4*)(wp + 4);
        float vv[8] = {v0.x, v0.y, v0.z, v0.w, v1.x, v1.y, v1.z, v1.w};
        unsigned hi4[4], lo4[4];
#pragma unroll
        for (int p = 0; p < 4; p++) {
            float l0, l1;
            hi4[p] = pack_hi(vv[2 * p], vv[2 * p + 1], l0, l1);
            lo4[p] = pack_lo(l0, l1);
        }
        *(uint4*)(Whi + (size_t)n * WROW + k * 2) = make_uint4(hi4[0], hi4[1], hi4[2], hi4[3]);
        *(uint4*)(Wlo + (size_t)n * WROW + k * 2) = make_uint4(lo4[0], lo4[1], lo4[2], lo4[3]);
    }

    // ---- per-thread state registers (thread b owns batch row b, cols base..base+8) ----
    float creg[8], hreg[8];
    if (tid < 64) {
#pragma unroll
        for (int u = 0; u < 8; u++) { creg[u] = c0[base + u]; hreg[u] = h0[base + u]; }
        // write initial h into g_hA[0]
        unsigned hi4[4], lo4[4]; float lb[8];
#pragma unroll
        for (int p = 0; p < 4; p++) hi4[p] = pack_hi(hreg[2 * p], hreg[2 * p + 1], lb[2 * p], lb[2 * p + 1]);
#pragma unroll
        for (int p = 0; p < 4; p++) lo4[p] = pack_lo(lb[2 * p], lb[2 * p + 1]);
        unsigned char* blk = g_hA[0] + ch_base * CHUNK_BYTES;
        *(uint4*)(blk + (size_t)tid * AROW + cb_base * 16)        = make_uint4(hi4[0], hi4[1], hi4[2], hi4[3]);
        *(uint4*)(blk + (size_t)(64 + tid) * AROW + cb_base * 16) = make_uint4(lo4[0], lo4[1], lo4[2], lo4[3]);
    }
    __syncthreads();
    if (tid == 0) {
        __threadfence();
        atomicAdd(&g_bar, 1u);
        while (*(volatile unsigned*)&g_bar < NBLK) { __nanosleep(64); }
    }
    __syncthreads();

    unsigned cntA[2] = {0, 0};
    int hiRow = w * 16 + g;          // A hi-plane row for this lane
    // fragment row base offsets (bytes) inside a chunk block
    unsigned offH0 = (unsigned)hiRow * AROW;
    unsigned offH1 = (unsigned)(hiRow + 8) * AROW;
    unsigned offL0 = (unsigned)(64 + hiRow) * AROW;
    unsigned offL1 = (unsigned)(64 + hiRow + 8) * AROW;

    for (int t = 0; t < TT; t++) {
        const unsigned char* src = g_hA[t & 1];

        // prologue: stage chunks 0,1
        if (tid == 0) {
            mbar_expect_tx(mbA[0], CHUNK_BYTES);
            bulk_cp(Abuf[0], src, CHUNK_BYTES, mbA[0]);
            mbar_expect_tx(mbA[1], CHUNK_BYTES);
            bulk_cp(Abuf[1], src + CHUNK_BYTES, CHUNK_BYTES, mbA[1]);
        }
        cntA[0]++; cntA[1]++;

        // prefetch xg + mask (overlaps with MMA work below)
        float xgv[32];
        int m = 0;
        if (tid < 64) {
            const float* xp = g_xg + ((size_t)tid * TT + t) * G4 + base;
#pragma unroll
            for (int gg = 0; gg < 4; gg++) {
                float4 a = *(const float4*)(xp + gg * HH);
                float4 bq = *(const float4*)(xp + gg * HH + 4);
                xgv[gg * 8 + 0] = a.x;  xgv[gg * 8 + 1] = a.y;  xgv[gg * 8 + 2] = a.z;  xgv[gg * 8 + 3] = a.w;
                xgv[gg * 8 + 4] = bq.x; xgv[gg * 8 + 5] = bq.y; xgv[gg * 8 + 6] = bq.z; xgv[gg * 8 + 7] = bq.w;
            }
            m = __ldg(mask + tid * TT + t);
        }

        float acc[4][4];
#pragma unroll
        for (int nt = 0; nt < 4; nt++)
#pragma unroll
            for (int i = 0; i < 4; i++) acc[nt][i] = 0.f;

        for (int ch = 0; ch < 8; ch++) {
            int buf = ch & 1;
            mbar_wait(mbA[buf], (cntA[buf] - 1) & 1);
            const char* Ab = Abuf[buf];

#pragma unroll
            for (int ks = 0; ks < 8; ks++) {
                unsigned cb = (unsigned)(ks * 32 + tig * 4);
                unsigned ah0 = *(const unsigned*)(Ab + offH0 + cb);
                unsigned ah2 = *(const unsigned*)(Ab + offH0 + cb + 16);
                unsigned ah1 = *(const unsigned*)(Ab + offH1 + cb);
                unsigned ah3 = *(const unsigned*)(Ab + offH1 + cb + 16);
                unsigned al0 = *(const unsigned*)(Ab + offL0 + cb);
                unsigned al2 = *(const unsigned*)(Ab + offL0 + cb + 16);
                unsigned al1 = *(const unsigned*)(Ab + offL1 + cb);
                unsigned al3 = *(const unsigned*)(Ab + offL1 + cb + 16);
                unsigned kb = (unsigned)((ch * 128 + ks * 16 + tig * 2) * 2);
#pragma unroll
                for (int nt = 0; nt < 4; nt++) {
                    const char* wh = Whi + (size_t)(nt * 8 + g) * WROW + kb;
                    const char* wl = Wlo + (size_t)(nt * 8 + g) * WROW + kb;
                    unsigned bh0 = *(const unsigned*)wh;
                    unsigned bh1 = *(const unsigned*)(wh + 16);
                    unsigned bl0 = *(const unsigned*)wl;
                    unsigned bl1 = *(const unsigned*)(wl + 16);
                    mma_bf16(acc[nt], ah0, ah1, ah2, ah3, bh0, bh1);
                    mma_bf16(acc[nt], ah0, ah1, ah2, ah3, bl0, bl1);
                    mma_bf16(acc[nt], al0, al1, al2, al3, bh0, bh1);
                }
            }
            __syncthreads();   // everyone done with buf before refill
            if (ch + 2 < 8) {
                if (tid == 0) {
                    mbar_expect_tx(mbA[buf], CHUNK_BYTES);
                    bulk_cp(Abuf[buf], src + (ch + 2) * CHUNK_BYTES, CHUNK_BYTES, mbA[buf]);
                }
                cntA[buf]++;
            }
        }

        // ---- stash D fragments: row = batch, col = gate col ----
#pragma unroll
        for (int nt = 0; nt < 4; nt++) {
            int col = nt * 8 + tig * 2;
            stash[(w * 16 + g) * 33 + col]     = acc[nt][0];
            stash[(w * 16 + g) * 33 + col + 1] = acc[nt][1];
            stash[(w * 16 + g + 8) * 33 + col]     = acc[nt][2];
            stash[(w * 16 + g + 8) * 33 + col + 1] = acc[nt][3];
        }
        __syncthreads();

        // ---- epilogue: thread b = batch row ----
        if (tid < 64) {
            int b = tid;
            float cn8[8], hn8[8];
#pragma unroll
            for (int u = 0; u < 8; u++) {
                float gi = stash[b * 33 + u]      + xgv[u];
                float gf = stash[b * 33 + 8 + u]  + xgv[8 + u];
                float gG = stash[b * 33 + 16 + u] + xgv[16 + u];
                float go = stash[b * 33 + 24 + u] + xgv[24 + u];
                float iv = sigm(gi);
                float fv = sigm(gf);
                float gv = tanhf(gG);
                float ov = sigm(go);
                float cn = fv * creg[u] + iv * gv;
                float hn = ov * tanhf(cn);
                cn8[u] = m ? cn : creg[u];
                hn8[u] = m ? hn : hreg[u];
                creg[u] = cn8[u];
                hreg[u] = hn8[u];
            }
            float* op = out + ((size_t)b * TT + t) * HH + base;
            *(float4*)op       = make_float4(hn8[0], hn8[1], hn8[2], hn8[3]);
            *(float4*)(op + 4) = make_float4(hn8[4], hn8[5], hn8[6], hn8[7]);
            unsigned hi4[4], lo4[4]; float lb[8];
#pragma unroll
            for (int p = 0; p < 4; p++) hi4[p] = pack_hi(hn8[2 * p], hn8[2 * p + 1], lb[2 * p], lb[2 * p + 1]);
#pragma unroll
            for (int p = 0; p < 4; p++) lo4[p] = pack_lo(lb[2 * p], lb[2 * p + 1]);
            unsigned char* blk = g_hA[(t + 1) & 1] + ch_base * CHUNK_BYTES;
            *(uint4*)(blk + (size_t)b * AROW + cb_base * 16)        = make_uint4(hi4[0], hi4[1], hi4[2], hi4[3]);
            *(uint4*)(blk + (size_t)(64 + b) * AROW + cb_base * 16) = make_uint4(lo4[0], lo4[1], lo4[2], lo4[3]);
        }

        // ---- grid barrier ----
        __syncthreads();
        if (tid == 0) {
            __threadfence();
            atomicAdd(&g_bar, 1u);
            unsigned want = (unsigned)(t + 2) * NBLK;
            while (*(volatile unsigned*)&g_bar < want) { __nanosleep(64); }
        }
        __syncthreads();
    }
}

// ---------------- launch ----------------
extern "C" void kernel_launch(void* const* d_in, const int* in_sizes, int n_in,
                              void* d_out, int out_size) {
    const float* x    = (const float*)d_in[0];
    const int*   mask = (const int*)  d_in[1];
    const float* Wih  = (const float*)d_in[2];
    const float* Whh  = (const float*)d_in[3];
    const float* bih  = (const float*)d_in[4];
    const float* bhh  = (const float*)d_in[5];
    const float* h0   = (const float*)d_in[6];
    const float* c0   = (const float*)d_in[7];
    float* out = (float*)d_out;

    cudaFuncSetAttribute(lstm_tc, cudaFuncAttributeMaxDynamicSharedMemorySize, SMEM_BYTES);

    xg_gemm<<<dim3(G4 / BN, (BB * TT) / BM), 256>>>(x, Wih, bih, bhh);
    lstm_tc<<<NBLK, 128, SMEM_BYTES>>>(Whh, mask, h0, c0, out);
}

// round 8
// speedup vs baseline: 2.0196x; 1.2268x over previous
#include <cuda_runtime.h>
#include <cuda_bf16.h>
#include <cstdint>
#include <math.h>

#define BB 64
#define TT 512
#define DD 512
#define HH 1024
#define G4 4096
#define NBLK 128

#define AROW 272                 // bytes per row in an h chunk block
#define CHUNK_BYTES (128 * AROW) // 34816
#define WROW 2064                // bytes per W_hh row in SMEM

// ---------------- device scratch ----------------
__device__ float g_xg[(size_t)BB * TT * G4];
__device__ __align__(16) unsigned char g_hA[2][8 * CHUNK_BYTES];
__device__ __nv_bfloat16 g_xhi[(size_t)BB * TT * DD];
__device__ __nv_bfloat16 g_xlo[(size_t)BB * TT * DD];
__device__ __nv_bfloat16 g_whi[(size_t)G4 * DD];
__device__ __nv_bfloat16 g_wlo[(size_t)G4 * DD];
__device__ unsigned g_bar;

// ---------------- helpers ----------------
__device__ __forceinline__ unsigned smem_u32(const void* p) {
    return (unsigned)__cvta_generic_to_shared(p);
}
__device__ __forceinline__ void mbar_init(unsigned a, unsigned n) {
    asm volatile("mbarrier.init.shared.b64 [%0], %1;" :: "r"(a), "r"(n) : "memory");
}
__device__ __forceinline__ void mbar_expect_tx(unsigned a, unsigned b) {
    asm volatile("mbarrier.arrive.expect_tx.shared.b64 _, [%0], %1;" :: "r"(a), "r"(b) : "memory");
}
__device__ __forceinline__ void mbar_wait(unsigned a, unsigned p) {
    asm volatile(
        "{\n\t.reg .pred P;\n"
        "W_%=:\n\t"
        "mbarrier.try_wait.parity.acquire.cta.shared::cta.b64 P, [%0], %1, 0x989680;\n\t"
        "@P bra D_%=;\n\t"
        "bra W_%=;\n"
        "D_%=:\n\t}" :: "r"(a), "r"(p) : "memory");
}
__device__ __forceinline__ void bulk_cp(void* sdst, const void* gsrc, unsigned bytes, unsigned mbar) {
    unsigned d = smem_u32(sdst);
    asm volatile(
        "cp.async.bulk.shared::cluster.global.mbarrier::complete_tx::bytes [%0], [%1], %2, [%3];"
        :: "r"(d), "l"(gsrc), "r"(bytes), "r"(mbar) : "memory");
}
__device__ __forceinline__ void cp16(void* sdst, const void* gsrc) {
    unsigned d = (unsigned)__cvta_generic_to_shared(sdst);
    asm volatile("cp.async.cg.shared.global [%0], [%1], 16;\n" :: "r"(d), "l"(gsrc));
}
__device__ __forceinline__ void cp_commit() {
    asm volatile("cp.async.commit_group;\n" ::: "memory");
}
__device__ __forceinline__ void cp_wait1() {
    asm volatile("cp.async.wait_group 1;\n" ::: "memory");
}
__device__ __forceinline__ void cp_wait0() {
    asm volatile("cp.async.wait_group 0;\n" ::: "memory");
}

__device__ __forceinline__ void mma_bf16(float* c, unsigned a0, unsigned a1, unsigned a2, unsigned a3,
                                         unsigned b0, unsigned b1) {
    asm volatile(
        "mma.sync.aligned.m16n8k16.row.col.f32.bf16.bf16.f32 "
        "{%0,%1,%2,%3}, {%4,%5,%6,%7}, {%8,%9}, {%0,%1,%2,%3};"
        : "+f"(c[0]), "+f"(c[1]), "+f"(c[2]), "+f"(c[3])
        : "r"(a0), "r"(a1), "r"(a2), "r"(a3), "r"(b0), "r"(b1));
}
__device__ __forceinline__ unsigned pack_hi(float v0, float v1, float& l0, float& l1) {
    __nv_bfloat16 h0 = __float2bfloat16_rn(v0), h1 = __float2bfloat16_rn(v1);
    l0 = v0 - __bfloat162float(h0);
    l1 = v1 - __bfloat162float(h1);
    unsigned short u0 = *(unsigned short*)&h0, u1 = *(unsigned short*)&h1;
    return (unsigned)u0 | ((unsigned)u1 << 16);
}
__device__ __forceinline__ unsigned pack_lo(float l0, float l1) {
    __nv_bfloat16 a = __float2bfloat16_rn(l0), b = __float2bfloat16_rn(l1);
    unsigned short u0 = *(unsigned short*)&a, u1 = *(unsigned short*)&b;
    return (unsigned)u0 | ((unsigned)u1 << 16);
}
__device__ __forceinline__ float sigm(float x) { return 1.f / (1.f + expf(-x)); }

// ---------------- cvt: fp32 -> bf16 hi/lo planes (x and W_ih) ----------------
#define XGROUPS (BB * TT * DD / 4)   // 4194304
#define WGROUPS (G4 * DD / 4)        // 524288
__global__ void cvt(const float* __restrict__ X, const float* __restrict__ Wih) {
    size_t i = (size_t)blockIdx.x * 256 + threadIdx.x;
    if (i == 0) g_bar = 0u;
    if (i >= XGROUPS + WGROUPS) return;
    const float* src;
    __nv_bfloat16 *hid, *lod;
    size_t gidx;
    if (i < XGROUPS) { src = X; hid = g_xhi; lod = g_xlo; gidx = i; }
    else             { src = Wih; hid = g_whi; lod = g_wlo; gidx = i - XGROUPS; }
    float4 v = ((const float4*)src)[gidx];
    float l0, l1, l2, l3;
    unsigned h01 = pack_hi(v.x, v.y, l0, l1);
    unsigned h23 = pack_hi(v.z, v.w, l2, l3);
    unsigned p01 = pack_lo(l0, l1);
    unsigned p23 = pack_lo(l2, l3);
    *(uint2*)(hid + gidx * 4) = make_uint2(h01, h23);
    *(uint2*)(lod + gidx * 4) = make_uint2(p01, p23);
}

// ---------------- xg HMMA GEMM: g_xg = x @ W_ih^T + biases ----------------
// BM=BN=128, K=512 in KC=64 chunks. 8 warps: wm=w&3 (M), wn=w>>2 (N); warp tile 32x64.
#define XROW 144
#define XPLANE (128 * XROW)          // 18432
#define XBUF (4 * XPLANE)            // 73728 per stage: Ahi|Alo|Bhi|Blo
#define XSMEM (2 * XBUF)             // 147456

__global__ __launch_bounds__(256, 1)
void xg_tc(const float* __restrict__ bih, const float* __restrict__ bhh) {
    extern __shared__ char xsm[];
    int tid = threadIdx.x;
    int w = tid >> 5, lane = tid & 31;
    int g = lane >> 2, tig = lane & 3;
    int wm = w & 3, wn = w >> 2;
    int bn = blockIdx.x, bm = blockIdx.y;

    float acc[2][8][4];
#pragma unroll
    for (int mf = 0; mf < 2; mf++)
#pragma unroll
        for (int nf = 0; nf < 8; nf++)
#pragma unroll
            for (int i = 0; i < 4; i++) acc[mf][nf][i] = 0.f;

    // stage chunk: 4096 x 16B chunks (Ahi, Alo, Bhi, Blo; 128 rows x 8 chunks each)
    auto stage = [&](int buf, int k0) {
        char* dst0 = xsm + buf * XBUF;
#pragma unroll
        for (int it = 0; it < 16; it++) {
            int i = it * 256 + tid;
            int plane = i >> 10;
            int r = (i >> 3) & 127;
            int q = i & 7;
            const __nv_bfloat16* srcb;
            int row;
            if (plane == 0)      { srcb = g_xhi; row = bm * 128 + r; }
            else if (plane == 1) { srcb = g_xlo; row = bm * 128 + r; }
            else if (plane == 2) { srcb = g_whi; row = bn * 128 + r; }
            else                 { srcb = g_wlo; row = bn * 128 + r; }
            cp16(dst0 + plane * XPLANE + r * XROW + q * 16,
                 srcb + (size_t)row * DD + k0 + q * 8);
        }
    };

    stage(0, 0);
    cp_commit();

    for (int ch = 0; ch < 8; ch++) {
        if (ch + 1 < 8) {
            stage((ch + 1) & 1, (ch + 1) * 64);
            cp_commit();
            cp_wait1();
        } else {
            cp_wait0();
        }
        __syncthreads();

        const char* Ah = xsm + (ch & 1) * XBUF;
        const char* Al = Ah + XPLANE;
        const char* Bh = Ah + 2 * XPLANE;
        const char* Bl = Ah + 3 * XPLANE;

#pragma unroll
        for (int ks = 0; ks < 4; ks++) {
            unsigned off = (unsigned)(ks * 32 + tig * 4);
            unsigned ah[2][4], al[2][4];
#pragma unroll
            for (int mf = 0; mf < 2; mf++) {
                const char* pa = Ah + (size_t)(wm * 32 + mf * 16 + g) * XROW + off;
                ah[mf][0] = *(const unsigned*)pa;
                ah[mf][2] = *(const unsigned*)(pa + 16);
                ah[mf][1] = *(const unsigned*)(pa + 8 * XROW);
                ah[mf][3] = *(const unsigned*)(pa + 8 * XROW + 16);
                const char* pl = Al + (size_t)(wm * 32 + mf * 16 + g) * XROW + off;
                al[mf][0] = *(const unsigned*)pl;
                al[mf][2] = *(const unsigned*)(pl + 16);
                al[mf][1] = *(const unsigned*)(pl + 8 * XROW);
                al[mf][3] = *(const unsigned*)(pl + 8 * XROW + 16);
            }
#pragma unroll
            for (int nf = 0; nf < 8; nf++) {
                const char* pb = Bh + (size_t)(wn * 64 + nf * 8 + g) * XROW + off;
                unsigned bh0 = *(const unsigned*)pb;
                unsigned bh1 = *(const unsigned*)(pb + 16);
                const char* pc = Bl + (size_t)(wn * 64 + nf * 8 + g) * XROW + off;
                unsigned bl0 = *(const unsigned*)pc;
                unsigned bl1 = *(const unsigned*)(pc + 16);
#pragma unroll
                for (int mf = 0; mf < 2; mf++) {
                    mma_bf16(acc[mf][nf], ah[mf][0], ah[mf][1], ah[mf][2], ah[mf][3], bh0, bh1);
                    mma_bf16(acc[mf][nf], ah[mf][0], ah[mf][1], ah[mf][2], ah[mf][3], bl0, bl1);
                    mma_bf16(acc[mf][nf], al[mf][0], al[mf][1], al[mf][2], al[mf][3], bh0, bh1);
                }
            }
        }
        __syncthreads();
    }

    // epilogue: bias + store fp32
#pragma unroll
    for (int nf = 0; nf < 8; nf++) {
        int col = bn * 128 + wn * 64 + nf * 8 + tig * 2;
        float bb0 = bih[col] + bhh[col];
        float bb1 = bih[col + 1] + bhh[col + 1];
#pragma unroll
        for (int mf = 0; mf < 2; mf++) {
            int row = bm * 128 + wm * 32 + mf * 16 + g;
            *(float2*)(g_xg + (size_t)row * G4 + col) =
                make_float2(acc[mf][nf][0] + bb0, acc[mf][nf][1] + bb1);
            *(float2*)(g_xg + (size_t)(row + 8) * G4 + col) =
                make_float2(acc[mf][nf][2] + bb0, acc[mf][nf][3] + bb1);
        }
    }
}

// ---------------- persistent HMMA LSTM (unchanged from round 7) ----------------
#define SM_A0 0
#define SM_A1 CHUNK_BYTES
#define SM_WHI (2 * CHUNK_BYTES)
#define SM_WLO (2 * CHUNK_BYTES + 32 * WROW)
#define SM_STASH (2 * CHUNK_BYTES + 64 * WROW)
#define SMEM_BYTES (SM_STASH + 8448 + 1024)

__global__ __launch_bounds__(128, 1)
void lstm_tc(const float* __restrict__ Whh, const int* __restrict__ mask,
             const float* __restrict__ h0, const float* __restrict__ c0,
             float* __restrict__ out) {
    extern __shared__ char smraw[];
    char* smb = (char*)(((uintptr_t)smraw + 1023) & ~(uintptr_t)1023);
    char* Abuf[2] = { smb + SM_A0, smb + SM_A1 };
    char* Whi = smb + SM_WHI;
    char* Wlo = smb + SM_WLO;
    float* stash = (float*)(smb + SM_STASH);

    __shared__ __align__(8) unsigned long long mbst[2];

    int tid = threadIdx.x;
    int w = tid >> 5, lane = tid & 31;
    int g = lane >> 2, tig = lane & 3;
    int base = blockIdx.x * 8;
    int ch_base = base >> 7;
    int cb_base = (base & 127) >> 3;

    unsigned mbA[2] = { smem_u32(&mbst[0]), smem_u32(&mbst[1]) };
    if (tid == 0) { mbar_init(mbA[0], 1); mbar_init(mbA[1], 1); }

    for (int idx = tid; idx < 32 * 128; idx += 128) {
        int n = idx >> 7, k = (idx & 127) * 8;
        int gg = n >> 3, u = n & 7;
        const float* wp = Whh + ((size_t)(gg * HH + base + u)) * HH + k;
        float4 v0 = *(const float4*)wp, v1 = *(const float4*)(wp + 4);
        float vv[8] = {v0.x, v0.y, v0.z, v0.w, v1.x, v1.y, v1.z, v1.w};
        unsigned hi4[4], lo4[4];
#pragma unroll
        for (int p = 0; p < 4; p++) {
            float l0, l1;
            hi4[p] = pack_hi(vv[2 * p], vv[2 * p + 1], l0, l1);
            lo4[p] = pack_lo(l0, l1);
        }
        *(uint4*)(Whi + (size_t)n * WROW + k * 2) = make_uint4(hi4[0], hi4[1], hi4[2], hi4[3]);
        *(uint4*)(Wlo + (size_t)n * WROW + k * 2) = make_uint4(lo4[0], lo4[1], lo4[2], lo4[3]);
    }

    float creg[8], hreg[8];
    if (tid < 64) {
#pragma unroll
        for (int u = 0; u < 8; u++) { creg[u] = c0[base + u]; hreg[u] = h0[base + u]; }
        unsigned hi4[4], lo4[4]; float lb[8];
#pragma unroll
        for (int p = 0; p < 4; p++) hi4[p] = pack_hi(hreg[2 * p], hreg[2 * p + 1], lb[2 * p], lb[2 * p + 1]);
#pragma unroll
        for (int p = 0; p < 4; p++) lo4[p] = pack_lo(lb[2 * p], lb[2 * p + 1]);
        unsigned char* blk = g_hA[0] + ch_base * CHUNK_BYTES;
        *(uint4*)(blk + (size_t)tid * AROW + cb_base * 16)        = make_uint4(hi4[0], hi4[1], hi4[2], hi4[3]);
        *(uint4*)(blk + (size_t)(64 + tid) * AROW + cb_base * 16) = make_uint4(lo4[0], lo4[1], lo4[2], lo4[3]);
    }
    __syncthreads();
    if (tid == 0) {
        __threadfence();
        atomicAdd(&g_bar, 1u);
        while (*(volatile unsigned*)&g_bar < NBLK) { __nanosleep(64); }
    }
    __syncthreads();

    unsigned cntA[2] = {0, 0};
    int hiRow = w * 16 + g;
    unsigned offH0 = (unsigned)hiRow * AROW;
    unsigned offH1 = (unsigned)(hiRow + 8) * AROW;
    unsigned offL0 = (unsigned)(64 + hiRow) * AROW;
    unsigned offL1 = (unsigned)(64 + hiRow + 8) * AROW;

    for (int t = 0; t < TT; t++) {
        const unsigned char* src = g_hA[t & 1];

        if (tid == 0) {
            mbar_expect_tx(mbA[0], CHUNK_BYTES);
            bulk_cp(Abuf[0], src, CHUNK_BYTES, mbA[0]);
            mbar_expect_tx(mbA[1], CHUNK_BYTES);
            bulk_cp(Abuf[1], src + CHUNK_BYTES, CHUNK_BYTES, mbA[1]);
        }
        cntA[0]++; cntA[1]++;

        float xgv[32];
        int m = 0;
        if (tid < 64) {
            const float* xp = g_xg + ((size_t)tid * TT + t) * G4 + base;
#pragma unroll
            for (int gg = 0; gg < 4; gg++) {
                float4 a = *(const float4*)(xp + gg * HH);
                float4 bq = *(const float4*)(xp + gg * HH + 4);
                xgv[gg * 8 + 0] = a.x;  xgv[gg * 8 + 1] = a.y;  xgv[gg * 8 + 2] = a.z;  xgv[gg * 8 + 3] = a.w;
                xgv[gg * 8 + 4] = bq.x; xgv[gg * 8 + 5] = bq.y; xgv[gg * 8 + 6] = bq.z; xgv[gg * 8 + 7] = bq.w;
            }
            m = __ldg(mask + tid * TT + t);
        }

        float acc[4][4];
#pragma unroll
        for (int nt = 0; nt < 4; nt++)
#pragma unroll
            for (int i = 0; i < 4; i++) acc[nt][i] = 0.f;

        for (int ch = 0; ch < 8; ch++) {
            int buf = ch & 1;
            mbar_wait(mbA[buf], (cntA[buf] - 1) & 1);
            const char* Ab = Abuf[buf];

#pragma unroll
            for (int ks = 0; ks < 8; ks++) {
                unsigned cb = (unsigned)(ks * 32 + tig * 4);
                unsigned ah0 = *(const unsigned*)(Ab + offH0 + cb);
                unsigned ah2 = *(const unsigned*)(Ab + offH0 + cb + 16);
                unsigned ah1 = *(const unsigned*)(Ab + offH1 + cb);
                unsigned ah3 = *(const unsigned*)(Ab + offH1 + cb + 16);
                unsigned al0 = *(const unsigned*)(Ab + offL0 + cb);
                unsigned al2 = *(const unsigned*)(Ab + offL0 + cb + 16);
                unsigned al1 = *(const unsigned*)(Ab + offL1 + cb);
                unsigned al3 = *(const unsigned*)(Ab + offL1 + cb + 16);
                unsigned kb = (unsigned)((ch * 128 + ks * 16 + tig * 2) * 2);
#pragma unroll
                for (int nt = 0; nt < 4; nt++) {
                    const char* wh = Whi + (size_t)(nt * 8 + g) * WROW + kb;
                    const char* wl = Wlo + (size_t)(nt * 8 + g) * WROW + kb;
                    unsigned bh0 = *(const unsigned*)wh;
                    unsigned bh1 = *(const unsigned*)(wh + 16);
                    unsigned bl0 = *(const unsigned*)wl;
                    unsigned bl1 = *(const unsigned*)(wl + 16);
                    mma_bf16(acc[nt], ah0, ah1, ah2, ah3, bh0, bh1);
                    mma_bf16(acc[nt], ah0, ah1, ah2, ah3, bl0, bl1);
                    mma_bf16(acc[nt], al0, al1, al2, al3, bh0, bh1);
                }
            }
            __syncthreads();
            if (ch + 2 < 8) {
                if (tid == 0) {
                    mbar_expect_tx(mbA[buf], CHUNK_BYTES);
                    bulk_cp(Abuf[buf], src + (ch + 2) * CHUNK_BYTES, CHUNK_BYTES, mbA[buf]);
                }
                cntA[buf]++;
            }
        }

#pragma unroll
        for (int nt = 0; nt < 4; nt++) {
            int col = nt * 8 + tig * 2;
            stash[(w * 16 + g) * 33 + col]     = acc[nt][0];
            stash[(w * 16 + g) * 33 + col + 1] = acc[nt][1];
            stash[(w * 16 + g + 8) * 33 + col]     = acc[nt][2];
            stash[(w * 16 + g + 8) * 33 + col + 1] = acc[nt][3];
        }
        __syncthreads();

        if (tid < 64) {
            int b = tid;
            float cn8[8], hn8[8];
#pragma unroll
            for (int u = 0; u < 8; u++) {
                float gi = stash[b * 33 + u]      + xgv[u];
                float gf = stash[b * 33 + 8 + u]  + xgv[8 + u];
                float gG = stash[b * 33 + 16 + u] + xgv[16 + u];
                float go = stash[b * 33 + 24 + u] + xgv[24 + u];
                float iv = sigm(gi);
                float fv = sigm(gf);
                float gv = tanhf(gG);
                float ov = sigm(go);
                float cn = fv * creg[u] + iv * gv;
                float hn = ov * tanhf(cn);
                cn8[u] = m ? cn : creg[u];
                hn8[u] = m ? hn : hreg[u];
                creg[u] = cn8[u];
                hreg[u] = hn8[u];
            }
            float* op = out + ((size_t)b * TT + t) * HH + base;
            *(float4*)op       = make_float4(hn8[0], hn8[1], hn8[2], hn8[3]);
            *(float4*)(op + 4) = make_float4(hn8[4], hn8[5], hn8[6], hn8[7]);
            unsigned hi4[4], lo4[4]; float lb[8];
#pragma unroll
            for (int p = 0; p < 4; p++) hi4[p] = pack_hi(hn8[2 * p], hn8[2 * p + 1], lb[2 * p], lb[2 * p + 1]);
#pragma unroll
            for (int p = 0; p < 4; p++) lo4[p] = pack_lo(lb[2 * p], lb[2 * p + 1]);
            unsigned char* blk = g_hA[(t + 1) & 1] + ch_base * CHUNK_BYTES;
            *(uint4*)(blk + (size_t)b * AROW + cb_base * 16)        = make_uint4(hi4[0], hi4[1], hi4[2], hi4[3]);
            *(uint4*)(blk + (size_t)(64 + b) * AROW + cb_base * 16) = make_uint4(lo4[0], lo4[1], lo4[2], lo4[3]);
        }

        __syncthreads();
        if (tid == 0) {
            __threadfence();
            atomicAdd(&g_bar, 1u);
            unsigned want = (unsigned)(t + 2) * NBLK;
            while (*(volatile unsigned*)&g_bar < want) { __nanosleep(64); }
        }
        __syncthreads();
    }
}

// ---------------- launch ----------------
extern "C" void kernel_launch(void* const* d_in, const int* in_sizes, int n_in,
                              void* d_out, int out_size) {
    const float* x    = (const float*)d_in[0];
    const int*   mask = (const int*)  d_in[1];
    const float* Wih  = (const float*)d_in[2];
    const float* Whh  = (const float*)d_in[3];
    const float* bih  = (const float*)d_in[4];
    const float* bhh  = (const float*)d_in[5];
    const float* h0   = (const float*)d_in[6];
    const float* c0   = (const float*)d_in[7];
    float* out = (float*)d_out;

    cudaFuncSetAttribute(xg_tc, cudaFuncAttributeMaxDynamicSharedMemorySize, XSMEM);
    cudaFuncSetAttribute(lstm_tc, cudaFuncAttributeMaxDynamicSharedMemorySize, SMEM_BYTES);

    cvt<<<(XGROUPS + WGROUPS + 255) / 256, 256>>>(x, Wih);
    xg_tc<<<dim3(G4 / 128, (BB * TT) / 128), 256, XSMEM>>>(bih, bhh);
    lstm_tc<<<NBLK, 128, SMEM_BYTES>>>(Whh, mask, h0, c0, out);
}

// round 9
// speedup vs baseline: 2.0698x; 1.0249x over previous
#include <cuda_runtime.h>
#include <cuda_bf16.h>
#include <cstdint>
#include <math.h>

#define BB 64
#define TT 512
#define DD 512
#define HH 1024
#define G4 4096
#define NBLK 128

#define AROW 272                 // bytes per row in an h chunk block
#define CHUNK_BYTES (128 * AROW) // 34816
#define WROW 2064                // bytes per W_hh row in SMEM

// ---------------- device scratch ----------------
__device__ float g_xg[(size_t)BB * TT * G4];
__device__ __align__(16) unsigned char g_hA[2][8 * CHUNK_BYTES];
// x as [bm(256)][ch(8)] swizzled tiles: 256 rows (128 hi + 128 lo) x 128 B = 32 KB
__device__ __align__(1024) unsigned char g_xA[(size_t)256 * 8 * 32768];
// W_ih as [bn(32)][ch(8)] swizzled tiles, same shape
__device__ __align__(1024) unsigned char g_wA[(size_t)32 * 8 * 32768];
__device__ unsigned g_bar;

// ---------------- helpers ----------------
__device__ __forceinline__ unsigned smem_u32(const void* p) {
    return (unsigned)__cvta_generic_to_shared(p);
}
__device__ __forceinline__ void mbar_init(unsigned a, unsigned n) {
    asm volatile("mbarrier.init.shared.b64 [%0], %1;" :: "r"(a), "r"(n) : "memory");
}
__device__ __forceinline__ void mbar_expect_tx(unsigned a, unsigned b) {
    asm volatile("mbarrier.arrive.expect_tx.shared.b64 _, [%0], %1;" :: "r"(a), "r"(b) : "memory");
}
__device__ __forceinline__ void mbar_wait(unsigned a, unsigned p) {
    asm volatile(
        "{\n\t.reg .pred P;\n"
        "W_%=:\n\t"
        "mbarrier.try_wait.parity.acquire.cta.shared::cta.b64 P, [%0], %1, 0x989680;\n\t"
        "@P bra D_%=;\n\t"
        "bra W_%=;\n"
        "D_%=:\n\t}" :: "r"(a), "r"(p) : "memory");
}
__device__ __forceinline__ void bulk_cp(void* sdst, const void* gsrc, unsigned bytes, unsigned mbar) {
    unsigned d = smem_u32(sdst);
    asm volatile(
        "cp.async.bulk.shared::cluster.global.mbarrier::complete_tx::bytes [%0], [%1], %2, [%3];"
        :: "r"(d), "l"(gsrc), "r"(bytes), "r"(mbar) : "memory");
}
__device__ __forceinline__ void mma_bf16(float* c, unsigned a0, unsigned a1, unsigned a2, unsigned a3,
                                         unsigned b0, unsigned b1) {
    asm volatile(
        "mma.sync.aligned.m16n8k16.row.col.f32.bf16.bf16.f32 "
        "{%0,%1,%2,%3}, {%4,%5,%6,%7}, {%8,%9}, {%0,%1,%2,%3};"
        : "+f"(c[0]), "+f"(c[1]), "+f"(c[2]), "+f"(c[3])
        : "r"(a0), "r"(a1), "r"(a2), "r"(a3), "r"(b0), "r"(b1));
}
__device__ __forceinline__ unsigned pack_hi(float v0, float v1, float& l0, float& l1) {
    __nv_bfloat16 h0 = __float2bfloat16_rn(v0), h1 = __float2bfloat16_rn(v1);
    l0 = v0 - __bfloat162float(h0);
    l1 = v1 - __bfloat162float(h1);
    unsigned short u0 = *(unsigned short*)&h0, u1 = *(unsigned short*)&h1;
    return (unsigned)u0 | ((unsigned)u1 << 16);
}
__device__ __forceinline__ unsigned pack_lo(float l0, float l1) {
    __nv_bfloat16 a = __float2bfloat16_rn(l0), b = __float2bfloat16_rn(l1);
    unsigned short u0 = *(unsigned short*)&a, u1 = *(unsigned short*)&b;
    return (unsigned)u0 | ((unsigned)u1 << 16);
}
__device__ __forceinline__ float sigm(float x) { return 1.f / (1.f + expf(-x)); }
// swizzled byte offset within a 256x128B tile
__device__ __forceinline__ unsigned swz(unsigned off) { return off ^ ((off >> 3) & 0x70); }
// swizzled address for fragment loads: row, 16B-slot, lane tig
__device__ __forceinline__ unsigned sadr(int row, int slot, int tig) {
    return (unsigned)(row * 128 + ((slot ^ (row & 7)) << 4) + tig * 4);
}

// ---------------- cvt: fp32 -> bf16 hi/lo swizzled chunk tiles ----------------
#define XN8 (BB * TT * DD / 8)   // 2097152
#define WN8 (G4 * DD / 8)        // 262144
__global__ void cvt(const float* __restrict__ X, const float* __restrict__ Wih) {
    size_t i = (size_t)blockIdx.x * 256 + threadIdx.x;
    if (i == 0) g_bar = 0u;
    if (i >= XN8 + WN8) return;
    const float* src;
    unsigned char* tile;
    size_t e;
    if (i < XN8) {
        e = i * 8;
        int rg = (int)(e >> 9);          // global row 0..32767
        int k = (int)(e & 511);
        tile = g_xA + ((size_t)((rg >> 7) * 8 + (k >> 6))) * 32768;
        src = X;
        int r = rg & 127, cb = (k & 63) * 2;
        float4 v0 = *(const float4*)(src + e);
        float4 v1 = *(const float4*)(src + e + 4);
        float l0, l1, l2, l3, l4, l5, l6, l7;
        unsigned h0 = pack_hi(v0.x, v0.y, l0, l1), h1 = pack_hi(v0.z, v0.w, l2, l3);
        unsigned h2 = pack_hi(v1.x, v1.y, l4, l5), h3 = pack_hi(v1.z, v1.w, l6, l7);
        *(uint4*)(tile + swz((unsigned)(r * 128 + cb))) = make_uint4(h0, h1, h2, h3);
        *(uint4*)(tile + swz((unsigned)((r + 128) * 128 + cb))) =
            make_uint4(pack_lo(l0, l1), pack_lo(l2, l3), pack_lo(l4, l5), pack_lo(l6, l7));
    } else {
        e = (i - XN8) * 8;
        int ng = (int)(e >> 9);          // W row 0..4095
        int k = (int)(e & 511);
        tile = g_wA + ((size_t)((ng >> 7) * 8 + (k >> 6))) * 32768;
        src = Wih;
        int r = ng & 127, cb = (k & 63) * 2;
        float4 v0 = *(const float4*)(src + e);
        float4 v1 = *(const float4*)(src + e + 4);
        float l0, l1, l2, l3, l4, l5, l6, l7;
        unsigned h0 = pack_hi(v0.x, v0.y, l0, l1), h1 = pack_hi(v0.z, v0.w, l2, l3);
        unsigned h2 = pack_hi(v1.x, v1.y, l4, l5), h3 = pack_hi(v1.z, v1.w, l6, l7);
        *(uint4*)(tile + swz((unsigned)(r * 128 + cb))) = make_uint4(h0, h1, h2, h3);
        *(uint4*)(tile + swz((unsigned)((r + 128) * 128 + cb))) =
            make_uint4(pack_lo(l0, l1), pack_lo(l2, l3), pack_lo(l4, l5), pack_lo(l6, l7));
    }
}

// ---------------- xg HMMA GEMM with bulk-TMA staging ----------------
// BM=BN=128, K=512 in 8 chunks of 64. Per chunk: 2 bulk copies (A tile, B tile).
#define XBUF 65536
#define XSMEM (2 * XBUF)

__global__ __launch_bounds__(256, 1)
void xg_tc(const float* __restrict__ bih, const float* __restrict__ bhh) {
    extern __shared__ __align__(128) char xsm[];
    __shared__ __align__(8) unsigned long long xmb[2];

    int tid = threadIdx.x;
    int w = tid >> 5, lane = tid & 31;
    int g = lane >> 2, tig = lane & 3;
    int wm = w & 3, wn = w >> 2;
    int bn = blockIdx.x, bm = blockIdx.y;

    unsigned mb[2] = { smem_u32(&xmb[0]), smem_u32(&xmb[1]) };
    if (tid == 0) { mbar_init(mb[0], 1); mbar_init(mb[1], 1); }
    __syncthreads();

    const unsigned char* asrc = g_xA + (size_t)bm * 8 * 32768;
    const unsigned char* bsrc = g_wA + (size_t)bn * 8 * 32768;

    auto stage = [&](int buf, int ch) {
        if (tid == 0) {
            mbar_expect_tx(mb[buf], 65536u);
            bulk_cp(xsm + buf * XBUF, asrc + ch * 32768, 32768u, mb[buf]);
            bulk_cp(xsm + buf * XBUF + 32768, bsrc + ch * 32768, 32768u, mb[buf]);
        }
    };

    float acc[2][8][4];
#pragma unroll
    for (int mf = 0; mf < 2; mf++)
#pragma unroll
        for (int nf = 0; nf < 8; nf++)
#pragma unroll
            for (int i = 0; i < 4; i++) acc[mf][nf][i] = 0.f;

    stage(0, 0);
    stage(1, 1);
    unsigned cnt[2] = {1, 1};

    for (int ch = 0; ch < 8; ch++) {
        int buf = ch & 1;
        mbar_wait(mb[buf], (cnt[buf] - 1) & 1);
        const char* Ab = xsm + buf * XBUF;
        const char* Bb = Ab + 32768;

#pragma unroll
        for (int ks = 0; ks < 4; ks++) {
            unsigned ah[2][4], al[2][4];
#pragma unroll
            for (int mf = 0; mf < 2; mf++) {
                int rh = wm * 32 + mf * 16 + g;
                ah[mf][0] = *(const unsigned*)(Ab + sadr(rh,       ks * 2,     tig));
                ah[mf][2] = *(const unsigned*)(Ab + sadr(rh,       ks * 2 + 1, tig));
                ah[mf][1] = *(const unsigned*)(Ab + sadr(rh + 8,   ks * 2,     tig));
                ah[mf][3] = *(const unsigned*)(Ab + sadr(rh + 8,   ks * 2 + 1, tig));
                al[mf][0] = *(const unsigned*)(Ab + sadr(rh + 128, ks * 2,     tig));
                al[mf][2] = *(const unsigned*)(Ab + sadr(rh + 128, ks * 2 + 1, tig));
                al[mf][1] = *(const unsigned*)(Ab + sadr(rh + 136, ks * 2,     tig));
                al[mf][3] = *(const unsigned*)(Ab + sadr(rh + 136, ks * 2 + 1, tig));
            }
#pragma unroll
            for (int nf = 0; nf < 8; nf++) {
                int rn = wn * 64 + nf * 8 + g;
                unsigned bh0 = *(const unsigned*)(Bb + sadr(rn,       ks * 2,     tig));
                unsigned bh1 = *(const unsigned*)(Bb + sadr(rn,       ks * 2 + 1, tig));
                unsigned bl0 = *(const unsigned*)(Bb + sadr(rn + 128, ks * 2,     tig));
                unsigned bl1 = *(const unsigned*)(Bb + sadr(rn + 128, ks * 2 + 1, tig));
#pragma unroll
                for (int mf = 0; mf < 2; mf++) {
                    mma_bf16(acc[mf][nf], ah[mf][0], ah[mf][1], ah[mf][2], ah[mf][3], bh0, bh1);
                    mma_bf16(acc[mf][nf], ah[mf][0], ah[mf][1], ah[mf][2], ah[mf][3], bl0, bl1);
                    mma_bf16(acc[mf][nf], al[mf][0], al[mf][1], al[mf][2], al[mf][3], bh0, bh1);
                }
            }
        }
        __syncthreads();
        if (ch + 2 < 8) {
            stage(buf, ch + 2);
            cnt[buf]++;
        }
    }

#pragma unroll
    for (int nf = 0; nf < 8; nf++) {
        int col = bn * 128 + wn * 64 + nf * 8 + tig * 2;
        float bb0 = bih[col] + bhh[col];
        float bb1 = bih[col + 1] + bhh[col + 1];
#pragma unroll
        for (int mf = 0; mf < 2; mf++) {
            int row = bm * 128 + wm * 32 + mf * 16 + g;
            *(float2*)(g_xg + (size_t)row * G4 + col) =
                make_float2(acc[mf][nf][0] + bb0, acc[mf][nf][1] + bb1);
            *(float2*)(g_xg + (size_t)(row + 8) * G4 + col) =
                make_float2(acc[mf][nf][2] + bb0, acc[mf][nf][3] + bb1);
        }
    }
}

// ---------------- persistent HMMA LSTM (unchanged from round 8) ----------------
#define SM_A0 0
#define SM_A1 CHUNK_BYTES
#define SM_WHI (2 * CHUNK_BYTES)
#define SM_WLO (2 * CHUNK_BYTES + 32 * WROW)
#define SM_STASH (2 * CHUNK_BYTES + 64 * WROW)
#define SMEM_BYTES (SM_STASH + 8448 + 1024)

__global__ __launch_bounds__(128, 1)
void lstm_tc(const float* __restrict__ Whh, const int* __restrict__ mask,
             const float* __restrict__ h0, const float* __restrict__ c0,
             float* __restrict__ out) {
    extern __shared__ char smraw[];
    char* smb = (char*)(((uintptr_t)smraw + 1023) & ~(uintptr_t)1023);
    char* Abuf[2] = { smb + SM_A0, smb + SM_A1 };
    char* Whi = smb + SM_WHI;
    char* Wlo = smb + SM_WLO;
    float* stash = (float*)(smb + SM_STASH);

    __shared__ __align__(8) unsigned long long mbst[2];

    int tid = threadIdx.x;
    int w = tid >> 5, lane = tid & 31;
    int g = lane >> 2, tig = lane & 3;
    int base = blockIdx.x * 8;
    int ch_base = base >> 7;
    int cb_base = (base & 127) >> 3;

    unsigned mbA[2] = { smem_u32(&mbst[0]), smem_u32(&mbst[1]) };
    if (tid == 0) { mbar_init(mbA[0], 1); mbar_init(mbA[1], 1); }

    for (int idx = tid; idx < 32 * 128; idx += 128) {
        int n = idx >> 7, k = (idx & 127) * 8;
        int gg = n >> 3, u = n & 7;
        const float* wp = Whh + ((size_t)(gg * HH + base + u)) * HH + k;
        float4 v0 = *(const float4*)wp, v1 = *(const float4*)(wp + 4);
        float vv[8] = {v0.x, v0.y, v0.z, v0.w, v1.x, v1.y, v1.z, v1.w};
        unsigned hi4[4], lo4[4];
#pragma unroll
        for (int p = 0; p < 4; p++) {
            float l0, l1;
            hi4[p] = pack_hi(vv[2 * p], vv[2 * p + 1], l0, l1);
            lo4[p] = pack_lo(l0, l1);
        }
        *(uint4*)(Whi + (size_t)n * WROW + k * 2) = make_uint4(hi4[0], hi4[1], hi4[2], hi4[3]);
        *(uint4*)(Wlo + (size_t)n * WROW + k * 2) = make_uint4(lo4[0], lo4[1], lo4[2], lo4[3]);
    }

    float creg[8], hreg[8];
    if (tid < 64) {
#pragma unroll
        for (int u = 0; u < 8; u++) { creg[u] = c0[base + u]; hreg[u] = h0[base + u]; }
        unsigned hi4[4], lo4[4]; float lb[8];
#pragma unroll
        for (int p = 0; p < 4; p++) hi4[p] = pack_hi(hreg[2 * p], hreg[2 * p + 1], lb[2 * p], lb[2 * p + 1]);
#pragma unroll
        for (int p = 0; p < 4; p++) lo4[p] = pack_lo(lb[2 * p], lb[2 * p + 1]);
        unsigned char* blk = g_hA[0] + ch_base * CHUNK_BYTES;
        *(uint4*)(blk + (size_t)tid * AROW + cb_base * 16)        = make_uint4(hi4[0], hi4[1], hi4[2], hi4[3]);
        *(uint4*)(blk + (size_t)(64 + tid) * AROW + cb_base * 16) = make_uint4(lo4[0], lo4[1], lo4[2], lo4[3]);
    }
    __syncthreads();
    if (tid == 0) {
        __threadfence();
        atomicAdd(&g_bar, 1u);
        while (*(volatile unsigned*)&g_bar < NBLK) { __nanosleep(64); }
    }
    __syncthreads();

    unsigned cntA[2] = {0, 0};
    int hiRow = w * 16 + g;
    unsigned offH0 = (unsigned)hiRow * AROW;
    unsigned offH1 = (unsigned)(hiRow + 8) * AROW;
    unsigned offL0 = (unsigned)(64 + hiRow) * AROW;
    unsigned offL1 = (unsigned)(64 + hiRow + 8) * AROW;

    for (int t = 0; t < TT; t++) {
        const unsigned char* src = g_hA[t & 1];

        if (tid == 0) {
            mbar_expect_tx(mbA[0], CHUNK_BYTES);
            bulk_cp(Abuf[0], src, CHUNK_BYTES, mbA[0]);
            mbar_expect_tx(mbA[1], CHUNK_BYTES);
            bulk_cp(Abuf[1], src + CHUNK_BYTES, CHUNK_BYTES, mbA[1]);
        }
        cntA[0]++; cntA[1]++;

        float xgv[32];
        int m = 0;
        if (tid < 64) {
            const float* xp = g_xg + ((size_t)tid * TT + t) * G4 + base;
#pragma unroll
            for (int gg = 0; gg < 4; gg++) {
                float4 a = *(const float4*)(xp + gg * HH);
                float4 bq = *(const float4*)(xp + gg * HH + 4);
                xgv[gg * 8 + 0] = a.x;  xgv[gg * 8 + 1] = a.y;  xgv[gg * 8 + 2] = a.z;  xgv[gg * 8 + 3] = a.w;
                xgv[gg * 8 + 4] = bq.x; xgv[gg * 8 + 5] = bq.y; xgv[gg * 8 + 6] = bq.z; xgv[gg * 8 + 7] = bq.w;
            }
            m = __ldg(mask + tid * TT + t);
        }

        float acc[4][4];
#pragma unroll
        for (int nt = 0; nt < 4; nt++)
#pragma unroll
            for (int i = 0; i < 4; i++) acc[nt][i] = 0.f;

        for (int ch = 0; ch < 8; ch++) {
            int buf = ch & 1;
            mbar_wait(mbA[buf], (cntA[buf] - 1) & 1);
            const char* Ab = Abuf[buf];

#pragma unroll
            for (int ks = 0; ks < 8; ks++) {
                unsigned cb = (unsigned)(ks * 32 + tig * 4);
                unsigned ah0 = *(const unsigned*)(Ab + offH0 + cb);
                unsigned ah2 = *(const unsigned*)(Ab + offH0 + cb + 16);
                unsigned ah1 = *(const unsigned*)(Ab + offH1 + cb);
                unsigned ah3 = *(const unsigned*)(Ab + offH1 + cb + 16);
                unsigned al0 = *(const unsigned*)(Ab + offL0 + cb);
                unsigned al2 = *(const unsigned*)(Ab + offL0 + cb + 16);
                unsigned al1 = *(const unsigned*)(Ab + offL1 + cb);
                unsigned al3 = *(const unsigned*)(Ab + offL1 + cb + 16);
                unsigned kb = (unsigned)((ch * 128 + ks * 16 + tig * 2) * 2);
#pragma unroll
                for (int nt = 0; nt < 4; nt++) {
                    const char* wh = Whi + (size_t)(nt * 8 + g) * WROW + kb;
                    const char* wl = Wlo + (size_t)(nt * 8 + g) * WROW + kb;
                    unsigned bh0 = *(const unsigned*)wh;
                    unsigned bh1 = *(const unsigned*)(wh + 16);
                    unsigned bl0 = *(const unsigned*)wl;
                    unsigned bl1 = *(const unsigned*)(wl + 16);
                    mma_bf16(acc[nt], ah0, ah1, ah2, ah3, bh0, bh1);
                    mma_bf16(acc[nt], ah0, ah1, ah2, ah3, bl0, bl1);
                    mma_bf16(acc[nt], al0, al1, al2, al3, bh0, bh1);
                }
            }
            __syncthreads();
            if (ch + 2 < 8) {
                if (tid == 0) {
                    mbar_expect_tx(mbA[buf], CHUNK_BYTES);
                    bulk_cp(Abuf[buf], src + (ch + 2) * CHUNK_BYTES, CHUNK_BYTES, mbA[buf]);
                }
                cntA[buf]++;
            }
        }

#pragma unroll
        for (int nt = 0; nt < 4; nt++) {
            int col = nt * 8 + tig * 2;
            stash[(w * 16 + g) * 33 + col]     = acc[nt][0];
            stash[(w * 16 + g) * 33 + col + 1] = acc[nt][1];
            stash[(w * 16 + g + 8) * 33 + col]     = acc[nt][2];
            stash[(w * 16 + g + 8) * 33 + col + 1] = acc[nt][3];
        }
        __syncthreads();

        if (tid < 64) {
            int b = tid;
            float cn8[8], hn8[8];
#pragma unroll
            for (int u = 0; u < 8; u++) {
                float gi = stash[b * 33 + u]      + xgv[u];
                float gf = stash[b * 33 + 8 + u]  + xgv[8 + u];
                float gG = stash[b * 33 + 16 + u] + xgv[16 + u];
                float go = stash[b * 33 + 24 + u] + xgv[24 + u];
                float iv = sigm(gi);
                float fv = sigm(gf);
                float gv = tanhf(gG);
                float ov = sigm(go);
                float cn = fv * creg[u] + iv * gv;
                float hn = ov * tanhf(cn);
                cn8[u] = m ? cn : creg[u];
                hn8[u] = m ? hn : hreg[u];
                creg[u] = cn8[u];
                hreg[u] = hn8[u];
            }
            float* op = out + ((size_t)b * TT + t) * HH + base;
            *(float4*)op       = make_float4(hn8[0], hn8[1], hn8[2], hn8[3]);
            *(float4*)(op + 4) = make_float4(hn8[4], hn8[5], hn8[6], hn8[7]);
            unsigned hi4[4], lo4[4]; float lb[8];
#pragma unroll
            for (int p = 0; p < 4; p++) hi4[p] = pack_hi(hn8[2 * p], hn8[2 * p + 1], lb[2 * p], lb[2 * p + 1]);
#pragma unroll
            for (int p = 0; p < 4; p++) lo4[p] = pack_lo(lb[2 * p], lb[2 * p + 1]);
            unsigned char* blk = g_hA[(t + 1) & 1] + ch_base * CHUNK_BYTES;
            *(uint4*)(blk + (size_t)b * AROW + cb_base * 16)        = make_uint4(hi4[0], hi4[1], hi4[2], hi4[3]);
            *(uint4*)(blk + (size_t)(64 + b) * AROW + cb_base * 16) = make_uint4(lo4[0], lo4[1], lo4[2], lo4[3]);
        }

        __syncthreads();
        if (tid == 0) {
            __threadfence();
            atomicAdd(&g_bar, 1u);
            unsigned want = (unsigned)(t + 2) * NBLK;
            while (*(volatile unsigned*)&g_bar < want) { __nanosleep(64); }
        }
        __syncthreads();
    }
}

// ---------------- launch ----------------
extern "C" void kernel_launch(void* const* d_in, const int* in_sizes, int n_in,
                              void* d_out, int out_size) {
    const float* x    = (const float*)d_in[0];
    const int*   mask = (const int*)  d_in[1];
    const float* Wih  = (const float*)d_in[2];
    const float* Whh  = (const float*)d_in[3];
    const float* bih  = (const float*)d_in[4];
    const float* bhh  = (const float*)d_in[5];
    const float* h0   = (const float*)d_in[6];
    const float* c0   = (const float*)d_in[7];
    float* out = (float*)d_out;

    cudaFuncSetAttribute(xg_tc, cudaFuncAttributeMaxDynamicSharedMemorySize, XSMEM);
    cudaFuncSetAttribute(lstm_tc, cudaFuncAttributeMaxDynamicSharedMemorySize, SMEM_BYTES);

    cvt<<<(XN8 + WN8 + 255) / 256, 256>>>(x, Wih);
    xg_tc<<<dim3(G4 / 128, (BB * TT) / 128), 256, XSMEM>>>(bih, bhh);
    lstm_tc<<<NBLK, 128, SMEM_BYTES>>>(Whh, mask, h0, c0, out);
}